// round 7
// baseline (speedup 1.0000x reference)
#include <cuda_runtime.h>
#include <cstdint>

// B=4, M_IN=16, M_OUT=32, C=32.  x:(4,16,32,32,32,32) fp32 -> out:(4,32,4,32) fp32
//
//   s1[b,m,c2] = sum_{c3,c4,c5} x          (s2 == s1)
//   s3[b,m,c3] = sum_{c2,c4,c5} x
//   s4[b,m,c4] = sum_{c2,c3,c5} x
//   W = alpha+beta+gamma+delta (16x32)
//   out[b,n,i,c] = sum_m S_i[b,m,c] * W[m,n],  S = [s1,s1,s3,s4]
//
// Kernel 1: EXACT R3 hot path (proven ~38us, ~88% HBM). Do not touch.
// Kernel 2: grid 256 = (bm,i). Stage A: one parallel L2 round trip per block
//   builds S[bm,i,c]. acq_rel ticket; the single last block (tick 255) runs
//   the whole einsum (16K outputs, 256 threads). Winner resets the counter.

__device__ float g_s1h[4096];            // [bm*64 + c2*2 + half]
__device__ float g_s3 [2048 * 32];       // [bm*1024 + c2*32 + c3] (full; unique owner half)
__device__ float g_s4h[4096 * 32];       // [(bm*64 + c2*2+half)*32 + c4] (partial)
__device__ float g_S  [8192];            // [bm][i][c]
__device__ int   cnt_tail;

__device__ __forceinline__ unsigned long long addx2(unsigned long long a,
                                                    unsigned long long b) {
    unsigned long long r;
    asm("add.rn.f32x2 %0, %1, %2;" : "=l"(r) : "l"(a), "l"(b));
    return r;
}
__device__ __forceinline__ float x2sum(unsigned long long a) {
    unsigned lo, hi;
    asm("mov.b64 {%0,%1}, %2;" : "=r"(lo), "=r"(hi) : "l"(a));
    return __uint_as_float(lo) + __uint_as_float(hi);
}
// evict-first 16B streaming load (read-once data; keep L2 for partials)
__device__ __forceinline__ ulonglong2 ldcs2(const ulonglong2* p) {
    ulonglong2 r;
    asm("ld.global.cs.v2.u64 {%0, %1}, [%2];" : "=l"(r.x), "=l"(r.y) : "l"(p));
    return r;
}
// gpu-scope acq_rel ticket
__device__ __forceinline__ int ticket(int* p) {
    int old;
    asm volatile("atom.acq_rel.gpu.global.add.s32 %0, [%1], 1;"
                 : "=r"(old) : "l"(p) : "memory");
    return old;
}

// ---------------- Kernel 1: half-slice reduction (R3, verbatim) ----------------
__global__ void __launch_bounds__(256, 4)
k_reduce(const float* __restrict__ x) {
    const int t    = threadIdx.x;
    const int lane = t & 31;
    const int w    = t >> 5;
    const int bid  = blockIdx.x;          // half-slice id
    const int slice = bid >> 1;
    const int half  = bid & 1;

    const ulonglong2* __restrict__ xv =
        reinterpret_cast<const ulonglong2*>(x) + (size_t)bid * 4096; // 16384 floats

    __shared__ float s4buf[256];          // [warp][c4]
    __shared__ float wt[8];

    unsigned long long col[8];
#pragma unroll
    for (int s = 0; s < 8; ++s) col[s] = 0ull;

    float rows_tot = 0.f;                 // valid on lane 0
#pragma unroll
    for (int j = 0; j < 2; ++j) {
        const int k = w + j * 8;          // local row 0..15  (c3 = half*16 + k)
        const ulonglong2* __restrict__ p = xv + k * 256 + lane;

        ulonglong2 d[8];
#pragma unroll
        for (int s = 0; s < 8; ++s) d[s] = ldcs2(p + s * 32);   // 8 back-to-back LDG.128

        unsigned long long row = 0ull;
#pragma unroll
        for (int s = 0; s < 8; ++s) {
            unsigned long long v = addx2(d[s].x, d[s].y);  // {f0+f2, f1+f3}
            row    = addx2(row, v);
            col[s] = addx2(col[s], v);
        }
        float r = x2sum(row);
#pragma unroll
        for (int o = 16; o; o >>= 1) r += __shfl_down_sync(0xffffffffu, r, o);
        if (lane == 0) {
            g_s3[slice * 32 + half * 16 + k] = r;   // full s3 entry (unique owner)
            rows_tot += r;
        }
    }

#pragma unroll
    for (int s = 0; s < 8; ++s) {
        float cs = x2sum(col[s]);
        cs += __shfl_down_sync(0xffffffffu, cs, 4);
        cs += __shfl_down_sync(0xffffffffu, cs, 2);
        cs += __shfl_down_sync(0xffffffffu, cs, 1);
        if ((lane & 7) == 0) s4buf[w * 32 + s * 4 + (lane >> 3)] = cs;
    }
    if (lane == 0) wt[w] = rows_tot;
    __syncthreads();

    if (t < 32) {        // warp 0: cross-warp s4 fold + slice total
        float v = 0.f;
#pragma unroll
        for (int ww = 0; ww < 8; ++ww) v += s4buf[ww * 32 + t];
        g_s4h[bid * 32 + t] = v;
        if (t == 0) {
            float s = 0.f;
#pragma unroll
            for (int ww = 0; ww < 8; ++ww) s += wt[ww];
            g_s1h[bid] = s;
        }
    }
}

// ---------------- Kernel 2: tail, grid 256 = (bm,i), winner does einsum ----------------
__global__ void __launch_bounds__(256)
k_tail(const float* __restrict__ wa, const float* __restrict__ wb,
       const float* __restrict__ wg, const float* __restrict__ wd,
       float* __restrict__ out) {
    __shared__ float pp[256];
    __shared__ float sW[512];
    __shared__ int   s_tick;

    const int t   = threadIdx.x;
    const int bid = blockIdx.x;
    const int i   = bid & 3;
    const int bm  = bid >> 2;

    // ---- stage A: build S[bm][i][c] in one parallel L2 round trip ----
    if (i < 2) {
        float v = (t < 64) ? __ldcg(&g_s1h[bm * 64 + t]) : 0.f;  // t = c2*2+half
        pp[t] = v;
        __syncthreads();
        if (t < 32) g_S[bm * 128 + i * 32 + t] = pp[2 * t] + pp[2 * t + 1];
    } else if (i == 2) {
        const int c = t & 31, part = t >> 5;     // part: 4 c2's each
        const float* __restrict__ p = g_s3 + bm * 1024 + part * 128 + c;
        float v = __ldcg(p) + __ldcg(p + 32) + __ldcg(p + 64) + __ldcg(p + 96);
        pp[t] = v;
        __syncthreads();
        if (t < 32) {
            float s = 0.f;
#pragma unroll
            for (int q = 0; q < 8; ++q) s += pp[t + 32 * q];
            g_S[bm * 128 + 64 + t] = s;
        }
    } else {
        const int c = t & 31, part = t >> 5;     // part: 8 (c2,half)'s each
        const float* __restrict__ p = g_s4h + bm * 2048 + part * 256 + c;
        float v = 0.f;
#pragma unroll
        for (int q = 0; q < 8; ++q) v += __ldcg(p + q * 32);
        pp[t] = v;
        __syncthreads();
        if (t < 32) {
            float s = 0.f;
#pragma unroll
            for (int q = 0; q < 8; ++q) s += pp[t + 32 * q];
            g_S[bm * 128 + 96 + t] = s;
        }
    }

    // ---- ticket: single winner proceeds ----
    __syncthreads();
    if (t == 0) s_tick = ticket(&cnt_tail);
    __syncthreads();
    if (s_tick != 255) return;

    // ---- stage B: full einsum, 256 threads, 64 outputs each ----
    sW[t]       = wa[t]       + wb[t]       + wg[t]       + wd[t];
    sW[t + 256] = wa[t + 256] + wb[t + 256] + wg[t + 256] + wd[t + 256];
    __syncthreads();

    const int combo = t >> 1;             // (i2, c)
    const int nh    = t & 1;
    const int i2 = combo >> 5;
    const int c  = combo & 31;
#pragma unroll
    for (int b = 0; b < 4; ++b) {
        float S[16];
#pragma unroll
        for (int m = 0; m < 16; ++m)
            S[m] = __ldcg(&g_S[(b * 16 + m) * 128 + i2 * 32 + c]);
#pragma unroll
        for (int n0 = 0; n0 < 16; ++n0) {
            const int n = nh * 16 + n0;
            float acc = 0.f;
#pragma unroll
            for (int m = 0; m < 16; ++m) acc += S[m] * sW[m * 32 + n];
            out[((b * 32 + n) * 4 + i2) * 32 + c] = acc;
        }
    }

    if (t == 0) cnt_tail = 0;   // all 256 ticked; safe reset for next graph replay
}

// ---------------- launch ----------------
extern "C" void kernel_launch(void* const* d_in, const int* in_sizes, int n_in,
                              void* d_out, int out_size) {
    const float* x     = (const float*)d_in[0];
    const float* alpha = (const float*)d_in[1];
    const float* beta  = (const float*)d_in[2];
    const float* gamma = (const float*)d_in[3];
    const float* delta = (const float*)d_in[4];

    k_reduce<<<4096, 256>>>(x);
    k_tail  <<<256, 256>>>(alpha, beta, gamma, delta, (float*)d_out);
}

// round 8
// speedup vs baseline: 1.7861x; 1.7861x over previous
#include <cuda_runtime.h>
#include <cstdint>

// B=4, M_IN=16, M_OUT=32, C=32.  x:(4,16,32,32,32,32) fp32 -> out:(4,32,4,32) fp32
//
//   s1[b,m,c2] = sum_{c3,c4,c5} x          (s2 == s1)
//   s3[b,m,c3] = sum_{c2,c4,c5} x
//   s4[b,m,c4] = sum_{c2,c3,c5} x
//   W = alpha+beta+gamma+delta (16x32)
//   out[b,n,i,c] = sum_m S_i[b,m,c] * W[m,n],  S = [s1,s1,s3,s4]
//
// R3 structure (proven 43.6us) + PDL overlap:
//   k_reduce (4096 blocks): R3 hot path verbatim; triggers programmatic
//     launch completion at the end.
//   k_tail (64 blocks, launched with programmaticStreamSerializationAllowed):
//     preloads W to smem BEFORE cudaGridDependencySynchronize() so launch
//     overhead + weight loads overlap k_reduce's drain wave.

__device__ float g_s1h[4096];            // [bid], bid = slice*2+half, slice=(b*16+m)*32+c2
__device__ float g_s3 [2048 * 32];       // [slice][c3]  (full over c4,c5; unique owner half)
__device__ float g_s4h[4096 * 32];       // [bid][c4]    (partial over this half's c3)

__device__ __forceinline__ unsigned long long addx2(unsigned long long a,
                                                    unsigned long long b) {
    unsigned long long r;
    asm("add.rn.f32x2 %0, %1, %2;" : "=l"(r) : "l"(a), "l"(b));
    return r;
}
__device__ __forceinline__ float x2sum(unsigned long long a) {
    unsigned lo, hi;
    asm("mov.b64 {%0,%1}, %2;" : "=r"(lo), "=r"(hi) : "l"(a));
    return __uint_as_float(lo) + __uint_as_float(hi);
}
// evict-first 16B streaming load (read-once data; keep L2 for partials)
__device__ __forceinline__ ulonglong2 ldcs2(const ulonglong2* p) {
    ulonglong2 r;
    asm("ld.global.cs.v2.u64 {%0, %1}, [%2];" : "=l"(r.x), "=l"(r.y) : "l"(p));
    return r;
}

// ---------------- Kernel 1: half-slice reduction (R3, verbatim) + PDL trigger ------------
__global__ void __launch_bounds__(256, 4)
k_reduce(const float* __restrict__ x) {
    const int t    = threadIdx.x;
    const int lane = t & 31;
    const int w    = t >> 5;
    const int bid  = blockIdx.x;          // half-slice id
    const int slice = bid >> 1;
    const int half  = bid & 1;

    const ulonglong2* __restrict__ xv =
        reinterpret_cast<const ulonglong2*>(x) + (size_t)bid * 4096; // 16384 floats

    __shared__ float s4buf[256];          // [warp][c4]
    __shared__ float wt[8];

    unsigned long long col[8];
#pragma unroll
    for (int s = 0; s < 8; ++s) col[s] = 0ull;

    float rows_tot = 0.f;                 // valid on lane 0
#pragma unroll
    for (int j = 0; j < 2; ++j) {
        const int k = w + j * 8;          // local row 0..15  (c3 = half*16 + k)
        const ulonglong2* __restrict__ p = xv + k * 256 + lane;

        ulonglong2 d[8];
#pragma unroll
        for (int s = 0; s < 8; ++s) d[s] = ldcs2(p + s * 32);   // 8 back-to-back LDG.128

        unsigned long long row = 0ull;
#pragma unroll
        for (int s = 0; s < 8; ++s) {
            unsigned long long v = addx2(d[s].x, d[s].y);  // {f0+f2, f1+f3}
            row    = addx2(row, v);
            col[s] = addx2(col[s], v);
        }
        float r = x2sum(row);
#pragma unroll
        for (int o = 16; o; o >>= 1) r += __shfl_down_sync(0xffffffffu, r, o);
        if (lane == 0) {
            g_s3[slice * 32 + half * 16 + k] = r;   // full s3 entry (unique owner)
            rows_tot += r;
        }
    }

#pragma unroll
    for (int s = 0; s < 8; ++s) {
        float cs = x2sum(col[s]);
        cs += __shfl_down_sync(0xffffffffu, cs, 4);
        cs += __shfl_down_sync(0xffffffffu, cs, 2);
        cs += __shfl_down_sync(0xffffffffu, cs, 1);
        if ((lane & 7) == 0) s4buf[w * 32 + s * 4 + (lane >> 3)] = cs;
    }
    if (lane == 0) wt[w] = rows_tot;
    __syncthreads();

    if (t < 32) {        // warp 0: cross-warp s4 fold + slice total
        float v = 0.f;
#pragma unroll
        for (int ww = 0; ww < 8; ++ww) v += s4buf[ww * 32 + t];
        g_s4h[bid * 32 + t] = v;
        if (t == 0) {
            float s = 0.f;
#pragma unroll
            for (int ww = 0; ww < 8; ++ww) s += wt[ww];
            g_s1h[bid] = s;
        }
    }

    // allow the dependent tail to start launching while we drain
    cudaTriggerProgrammaticLaunchCompletion();
}

// ---------------- Kernel 2: tail (R3 structure), PDL-overlapped ----------------
// block bid: b = bid>>4, i = (bid>>2)&3, oct = bid&3 (c in [oct*8, oct*8+8))
__global__ void __launch_bounds__(256)
k_tail(const float* __restrict__ a, const float* __restrict__ bb,
       const float* __restrict__ g, const float* __restrict__ d,
       float* __restrict__ out) {
    __shared__ float sW[512];             // [m][n]
    __shared__ float pp[256];
    __shared__ float sS[128];             // [m][cl]

    const int t   = threadIdx.x;
    const int bid = blockIdx.x;
    const int b   = bid >> 4;
    const int i   = (bid >> 2) & 3;
    const int oct = bid & 3;

    // ---- overlap zone: weights are kernel inputs, independent of k_reduce ----
    sW[t]       = a[t]       + bb[t]       + g[t]       + d[t];
    sW[t + 256] = a[t + 256] + bb[t + 256] + g[t + 256] + d[t + 256];

    // wait for k_reduce's partials to be complete & visible
    cudaGridDependencySynchronize();

    // ---- stage A: build S[m][cl] (2 threads per value; R3-proven pattern) ----
    const int pair = t >> 1;              // 0..127
    const int part = t & 1;
    const int m    = pair >> 3;           // 0..15
    const int cl   = pair & 7;
    const int c    = oct * 8 + cl;
    const int bm   = b * 16 + m;

    float v = 0.f;
    if (i < 2) {
        v = g_s1h[(bm * 32 + c) * 2 + part];           // c plays c2; part = half
    } else if (i == 2) {
        const float* __restrict__ p = g_s3 + bm * 1024 + (part * 16) * 32 + c;
#pragma unroll
        for (int q = 0; q < 16; ++q) v += p[q * 32];   // over c2
    } else {
        const float* __restrict__ p = g_s4h + bm * 2048 + (part * 32) * 32 + c;
#pragma unroll
        for (int q = 0; q < 32; ++q) v += p[q * 32];   // over (c2,half)
    }
    pp[t] = v;
    __syncthreads();
    if (t < 128) sS[t] = pp[2 * t] + pp[2 * t + 1];
    __syncthreads();

    // ---- stage B: out[b,n,i,c] = sum_m S[m][cl] * W[m,n] ----
    const int n  = t >> 3;                // 0..31
    const int c2 = t & 7;                 // cl
    float acc = 0.f;
#pragma unroll
    for (int mm = 0; mm < 16; ++mm)
        acc += sS[mm * 8 + c2] * sW[mm * 32 + n];
    out[((b * 32 + n) * 4 + i) * 32 + oct * 8 + c2] = acc;
}

// ---------------- launch ----------------
extern "C" void kernel_launch(void* const* d_in, const int* in_sizes, int n_in,
                              void* d_out, int out_size) {
    const float* x     = (const float*)d_in[0];
    const float* alpha = (const float*)d_in[1];
    const float* beta  = (const float*)d_in[2];
    const float* gamma = (const float*)d_in[3];
    const float* delta = (const float*)d_in[4];

    k_reduce<<<4096, 256>>>(x);

    // dependent launch with programmatic stream serialization (PDL overlap)
    cudaLaunchConfig_t cfg = {};
    cfg.gridDim  = dim3(64, 1, 1);
    cfg.blockDim = dim3(256, 1, 1);
    cfg.dynamicSmemBytes = 0;
    cfg.stream = 0;                        // legacy default stream (same as <<<>>>)
    cudaLaunchAttribute at[1];
    at[0].id = cudaLaunchAttributeProgrammaticStreamSerialization;
    at[0].val.programmaticStreamSerializationAllowed = 1;
    cfg.attrs = at;
    cfg.numAttrs = 1;
    cudaLaunchKernelEx(&cfg, k_tail, alpha, beta, gamma, delta, (float*)d_out);
}